// round 13
// baseline (speedup 1.0000x reference)
#include <cstdint>
#include <cuda_runtime.h>
#include <cuda_bf16.h>
#include <mma.h>

using namespace nvcuda;
typedef __nv_bfloat16 bf16;

#define NN 50000
#define NPAD 50048
#define EE 600000
#define HH 128
#define GG 64
#define APAD 40
#define BPAD 136
#define CP   136
#define NCHUNK 196
#define STAGE_BYTES 18944   // 128*APAD*2 (10240) + 32*BPAD*2 (8704)

// ---------------- static scratch ----------------
__device__ __align__(16) float d_h[NN * HH];
__device__ __align__(16) float d_tmp[NPAD * HH];
__device__ __align__(16) bf16  d_xhi[NN * HH];
__device__ __align__(16) bf16  d_xlo[NN * HH];
__device__ __align__(16) bf16  d_ahi[NN * HH];
__device__ __align__(16) bf16  d_alo[NN * HH];
__device__ __align__(16) bf16  d_Whi[5 * 256 * HH];
__device__ __align__(16) bf16  d_Wlo[5 * 256 * HH];
__device__ int   d_rowptr[3 * (NN + 1)];
__device__ int   d_cur[3 * NN];
__device__ int   d_csum[3 * NCHUNK];
__device__ int   d_ssrc[3 * EE];
__device__ float d_invc[3 * NN];
__device__ __align__(16) float d_g[GG * HH];

// ---------------- helpers ----------------
__device__ __forceinline__ uint32_t smem_u32(const void* p) {
    uint32_t a;
    asm("{ .reg .u64 t; cvta.to.shared.u64 t, %1; cvt.u32.u64 %0, t; }"
        : "=r"(a) : "l"(p));
    return a;
}
__device__ __forceinline__ void cp16(uint32_t dst, const void* src) {
    asm volatile("cp.async.cg.shared.global [%0], [%1], 16;"
                 :: "r"(dst), "l"(src) : "memory");
}
#define CP_COMMIT() asm volatile("cp.async.commit_group;" ::: "memory")
template <int N> __device__ __forceinline__ void cp_wait() {
    asm volatile("cp.async.wait_group %0;" :: "n"(N) : "memory");
}

__device__ __forceinline__ void split4(float4 v, uint2& uh, uint2& ul) {
    bf16 hx = __float2bfloat16_rn(v.x), hy = __float2bfloat16_rn(v.y);
    bf16 hz = __float2bfloat16_rn(v.z), hw = __float2bfloat16_rn(v.w);
    bf16 lx = __float2bfloat16_rn(v.x - __bfloat162float(hx));
    bf16 ly = __float2bfloat16_rn(v.y - __bfloat162float(hy));
    bf16 lz = __float2bfloat16_rn(v.z - __bfloat162float(hz));
    bf16 lw = __float2bfloat16_rn(v.w - __bfloat162float(hw));
    __nv_bfloat162 a = __halves2bfloat162(hx, hy);
    __nv_bfloat162 b = __halves2bfloat162(hz, hw);
    __nv_bfloat162 c = __halves2bfloat162(lx, ly);
    __nv_bfloat162 d = __halves2bfloat162(lz, lw);
    uh.x = *(unsigned int*)&a; uh.y = *(unsigned int*)&b;
    ul.x = *(unsigned int*)&c; ul.y = *(unsigned int*)&d;
}

// ---------------- utility ----------------
__global__ void zero_int_kernel(int* __restrict__ p, int n) {
    int i = blockIdx.x * blockDim.x + threadIdx.x;
    if (i < n) p[i] = 0;
}
__global__ void zero_float_kernel(float* __restrict__ p, int n) {
    int i = blockIdx.x * blockDim.x + threadIdx.x;
    if (i < n) p[i] = 0.0f;
}

// ---------------- CSR build ----------------
__global__ void hist3_kernel(const int* __restrict__ e0, const int* __restrict__ e1,
                             const int* __restrict__ e2, int* __restrict__ cnt) {
    int e = blockIdx.x * blockDim.x + threadIdx.x;
    if (e >= 3 * EE) return;
    int s = e / EE, le = e - s * EE;
    const int* dst = (s == 0 ? e0 : (s == 1 ? e1 : e2)) + EE;
    atomicAdd(&cnt[s * NN + dst[le]], 1);
}

__global__ void chunksum_kernel(const int* __restrict__ cur, int* __restrict__ csum) {
    int blk = blockIdx.x, s = blk / NCHUNK, c = blk - s * NCHUNK;
    int tid = threadIdx.x;
    int i = c * 256 + tid;
    int v = (i < NN) ? cur[s * NN + i] : 0;
#pragma unroll
    for (int o = 16; o > 0; o >>= 1) v += __shfl_down_sync(0xffffffffu, v, o);
    __shared__ int ws[8];
    if ((tid & 31) == 0) ws[tid >> 5] = v;
    __syncthreads();
    if (tid == 0) {
        int t = 0;
#pragma unroll
        for (int k = 0; k < 8; k++) t += ws[k];
        csum[s * NCHUNK + c] = t;
    }
}

__global__ void chunkscan_kernel(int* __restrict__ csum, int* __restrict__ rowptr_all) {
    int s = blockIdx.x, t = threadIdx.x;
    __shared__ int sh[256];
    int v = (t < NCHUNK) ? csum[s * NCHUNK + t] : 0;
    sh[t] = v;
    __syncthreads();
    for (int o = 1; o < 256; o <<= 1) {
        int x = (t >= o) ? sh[t - o] : 0;
        __syncthreads();
        sh[t] += x;
        __syncthreads();
    }
    if (t < NCHUNK) csum[s * NCHUNK + t] = sh[t] - v;
    if (t == NCHUNK - 1) rowptr_all[s * (NN + 1) + NN] = sh[t];
}

__global__ void applyscan_kernel(const int* __restrict__ csum, int* __restrict__ cur,
                                 int* __restrict__ rowptr_all, float* __restrict__ invc_all) {
    int blk = blockIdx.x, s = blk / NCHUNK, c = blk - s * NCHUNK;
    int tid = threadIdx.x, lane = tid & 31, w = tid >> 5;
    int i = c * 256 + tid;
    int v = (i < NN) ? cur[s * NN + i] : 0;
    int x = v;
#pragma unroll
    for (int o = 1; o < 32; o <<= 1) {
        int y = __shfl_up_sync(0xffffffffu, x, o);
        if (lane >= o) x += y;
    }
    __shared__ int wsum[8];
    __shared__ int wexcl[8];
    if (lane == 31) wsum[w] = x;
    __syncthreads();
    if (tid == 0) {
        int run = 0;
#pragma unroll
        for (int k = 0; k < 8; k++) { wexcl[k] = run; run += wsum[k]; }
    }
    __syncthreads();
    int excl = x - v + wexcl[w] + csum[s * NCHUNK + c];
    if (i < NN) {
        rowptr_all[s * (NN + 1) + i] = excl;
        cur[s * NN + i] = excl;
        invc_all[s * NN + i] = 1.0f / (float)((v > 0) ? v : 1);
    }
}

__global__ void fill3_kernel(const int* __restrict__ e0, const int* __restrict__ e1,
                             const int* __restrict__ e2,
                             int* __restrict__ cur, int* __restrict__ ssrc) {
    int e = blockIdx.x * blockDim.x + threadIdx.x;
    if (e >= 3 * EE) return;
    int s = e / EE, le = e - s * EE;
    const int* es = (s == 0 ? e0 : (s == 1 ? e1 : e2));
    int p = atomicAdd(&cur[s * NN + es[EE + le]], 1);
    ssrc[(size_t)s * EE + p] = es[le];
}

// ---------------- weight stack + split ----------------
__global__ void convW_kernel(const float* __restrict__ Wl, const float* __restrict__ Wr,
                             bf16* __restrict__ oh, bf16* __restrict__ ol) {
    int idx = blockIdx.x * blockDim.x + threadIdx.x;
    if (idx >= 256 * 32) return;
    int r = idx >> 5, q = idx & 31;
    const float* src = (r < 128) ? (Wl + r * HH) : (Wr + (r - 128) * HH);
    float4 v = ((const float4*)src)[q];
    uint2 uh, ul;
    split4(v, uh, ul);
    *(uint2*)(oh + r * HH + q * 4) = uh;
    *(uint2*)(ol + r * HH + q * 4) = ul;
}

__global__ void convX_kernel(const float* __restrict__ x,
                             bf16* __restrict__ oh, bf16* __restrict__ ol) {
    int i = blockIdx.x * blockDim.x + threadIdx.x;
    if (i >= NN * 32) return;
    float4 v = ((const float4*)x)[i];
    uint2 uh, ul;
    split4(v, uh, ul);
    *(uint2*)(oh + (size_t)i * 4) = uh;
    *(uint2*)(ol + (size_t)i * 4) = ul;
}

// ---------------- pipelined wmma core: acc += A@W[bbase..] (3 splits) -----
__device__ __forceinline__ void gemm_core(
    const bf16* __restrict__ Ahi, const bf16* __restrict__ Alo,
    const bf16* __restrict__ Wh, const bf16* __restrict__ Wl_,
    int bbase, int row0, char* dsm, uint32_t sbu,
    wmma::fragment<wmma::accumulator, 16, 16, 16, float> (&acc)[2][4]) {
    const int tid = threadIdx.x;
    const int warp = tid >> 5;
    const int wr = warp >> 1, wc = warp & 1;

    auto stage = [&](int s) {
        int p = s >> 2, kb = s & 3;
        const bf16* Av = (p == 2) ? Alo : Ahi;
        const bf16* Bv = (p == 1) ? Wl_ : Wh;
        uint32_t bufA = sbu + 1024 + (s & 1) * STAGE_BYTES;
        uint32_t bufB = bufA + 10240;
        int idx = tid;
#pragma unroll
        for (int q = 0; q < 2; q++, idx += 256) {
            int r = idx >> 2, c4 = idx & 3;
            uint32_t dst = bufA + r * 80 + c4 * 16;
            int grow = row0 + r;
            if (grow < NN)
                cp16(dst, Av + (size_t)grow * HH + kb * 32 + c4 * 8);
            else
                asm volatile("st.shared.v4.b32 [%0], {%1,%1,%1,%1};"
                             :: "r"(dst), "r"(0u) : "memory");
        }
        idx = tid;
#pragma unroll
        for (int q = 0; q < 2; q++, idx += 256) {
            int r = idx >> 4, c16 = idx & 15;
            uint32_t dst = bufB + r * 272 + c16 * 16;
            cp16(dst, Bv + (size_t)(bbase + kb * 32 + r) * HH + c16 * 8);
        }
        CP_COMMIT();
    };

    stage(0);
    stage(1);
    for (int s = 0; s < 12; s++) {
        if (s < 11) cp_wait<1>(); else cp_wait<0>();
        __syncthreads();
        bf16* sA = (bf16*)(dsm + 1024 + (s & 1) * STAGE_BYTES);
        bf16* sB = (bf16*)(dsm + 1024 + (s & 1) * STAGE_BYTES + 10240);
#pragma unroll
        for (int ks = 0; ks < 32; ks += 16) {
            wmma::fragment<wmma::matrix_a, 16, 16, 16, bf16, wmma::row_major> fa[2];
#pragma unroll
            for (int i = 0; i < 2; i++)
                wmma::load_matrix_sync(fa[i], &sA[(wr * 32 + i * 16) * APAD + ks], APAD);
#pragma unroll
            for (int j = 0; j < 4; j++) {
                wmma::fragment<wmma::matrix_b, 16, 16, 16, bf16, wmma::row_major> fb;
                wmma::load_matrix_sync(fb, &sB[ks * BPAD + wc * 64 + j * 16], BPAD);
#pragma unroll
                for (int i = 0; i < 2; i++)
                    wmma::mma_sync(acc[i][j], fa[i], fb, acc[i][j]);
            }
        }
        __syncthreads();
        if (s + 2 < 12) stage(s + 2);
    }
}

// ---------------- k1: heterogeneous gather || x-side gemm -----------------
// blocks with blockIdx%17==0 (391) run x@Wr -> tmp; the other 6250 gather.
__global__ void __launch_bounds__(256) layer_k1(
    const float* __restrict__ cin,
    const int* __restrict__ rowptr, const int* __restrict__ ssrc,
    const float* __restrict__ invc,
    bf16* __restrict__ ahi, bf16* __restrict__ alo,
    const bf16* __restrict__ xh, const bf16* __restrict__ xl,
    const bf16* __restrict__ Wh, const bf16* __restrict__ Wl_,
    float* __restrict__ tmp) {
    extern __shared__ char dsm[];
    int b = blockIdx.x;
    if (b % 17 == 0) {
        uint32_t sbu = smem_u32(dsm);
        int row0 = (b / 17) * 128;
        wmma::fragment<wmma::accumulator, 16, 16, 16, float> acc[2][4];
#pragma unroll
        for (int i = 0; i < 2; i++)
#pragma unroll
            for (int j = 0; j < 4; j++) wmma::fill_fragment(acc[i][j], 0.0f);
        gemm_core(xh, xl, Wh, Wl_, 128, row0, dsm, sbu, acc);
        const int warp = threadIdx.x >> 5;
        const int wr = warp >> 1, wc = warp & 1;
#pragma unroll
        for (int i = 0; i < 2; i++)
#pragma unroll
            for (int j = 0; j < 4; j++)
                wmma::store_matrix_sync(
                    &tmp[(size_t)(row0 + wr * 32 + i * 16) * HH + wc * 64 + j * 16],
                    acc[i][j], HH, wmma::mem_row_major);
    } else {
        int gid = b - b / 17 - 1;
        int lane = threadIdx.x & 31;
        int node = gid * 8 + (threadIdx.x >> 5);
        if (node >= NN) return;
        const float4* X = (const float4*)cin;
        int beg = rowptr[node], end = rowptr[node + 1];
        float4 acc = make_float4(0.f, 0.f, 0.f, 0.f);
        int e = beg;
        for (; e + 2 <= end; e += 2) {
            int s0 = ssrc[e], s1 = ssrc[e + 1];
            float4 v0 = X[s0 * 32 + lane];
            float4 v1 = X[s1 * 32 + lane];
            acc.x += v0.x + v1.x;
            acc.y += v0.y + v1.y;
            acc.z += v0.z + v1.z;
            acc.w += v0.w + v1.w;
        }
        if (e < end) {
            int s = ssrc[e];
            float4 v = X[s * 32 + lane];
            acc.x += v.x; acc.y += v.y; acc.z += v.z; acc.w += v.w;
        }
        float ic = invc[node];
        float4 o = make_float4(acc.x * ic, acc.y * ic, acc.z * ic, acc.w * ic);
        uint2 uh, ul;
        split4(o, uh, ul);
        *(uint2*)(ahi + (size_t)node * HH + lane * 4) = uh;
        *(uint2*)(alo + (size_t)node * HH + lane * 4) = ul;
    }
}

// ---------------- k2: agg-side gemm + tmp + bias + norm + writeback -------
__global__ void __launch_bounds__(256) layer_k2(
    const bf16* __restrict__ ahi, const bf16* __restrict__ alo,
    const bf16* __restrict__ Wh, const bf16* __restrict__ Wl_,
    const float* __restrict__ tmp, const float* __restrict__ bias, int donorm,
    float* __restrict__ hout, bf16* __restrict__ ohi, bf16* __restrict__ olo) {
    extern __shared__ char dsm[];
    uint32_t sbu = smem_u32(dsm);
    float* sbias = (float*)dsm;
    const int tid = threadIdx.x;
    const int warp = tid >> 5, lane = tid & 31;
    const int wr = warp >> 1, wc = warp & 1;
    const int row0 = blockIdx.x * 128;

    if (tid < 128) sbias[tid] = bias[tid];

    wmma::fragment<wmma::accumulator, 16, 16, 16, float> acc[2][4];
#pragma unroll
    for (int i = 0; i < 2; i++)
#pragma unroll
        for (int j = 0; j < 4; j++) wmma::fill_fragment(acc[i][j], 0.0f);

    gemm_core(ahi, alo, Wh, Wl_, 0, row0, dsm, sbu, acc);

    float* tile = (float*)(dsm + 1024);
#pragma unroll
    for (int i = 0; i < 2; i++)
#pragma unroll
        for (int j = 0; j < 4; j++)
            wmma::store_matrix_sync(&tile[(wr * 32 + i * 16) * CP + wc * 64 + j * 16],
                                    acc[i][j], CP, wmma::mem_row_major);
    __syncthreads();

    float4 bb = *(float4*)&sbias[lane * 4];
#pragma unroll 2
    for (int rr = 0; rr < 16; rr++) {
        int r = warp * 16 + rr;
        int grow = row0 + r;
        float4 v = *(float4*)&tile[r * CP + lane * 4];
        float4 t = make_float4(0.f, 0.f, 0.f, 0.f);
        if (grow < NN) t = *(const float4*)&tmp[(size_t)grow * HH + lane * 4];
        v.x += t.x + bb.x; v.y += t.y + bb.y;
        v.z += t.z + bb.z; v.w += t.w + bb.w;
        float inv = 1.0f;
        if (donorm) {
            float ss = v.x * v.x + v.y * v.y + v.z * v.z + v.w * v.w;
            ss += __shfl_xor_sync(0xffffffffu, ss, 1);
            ss += __shfl_xor_sync(0xffffffffu, ss, 2);
            ss += __shfl_xor_sync(0xffffffffu, ss, 4);
            ss += __shfl_xor_sync(0xffffffffu, ss, 8);
            ss += __shfl_xor_sync(0xffffffffu, ss, 16);
            inv = 1.0f / fmaxf(sqrtf(ss), 1e-12f);
        }
        if (grow < NN) {
            v.x *= inv; v.y *= inv; v.z *= inv; v.w *= inv;
            size_t off = (size_t)grow * HH + lane * 4;
            *(float4*)(hout + off) = v;
            uint2 uh, ul;
            split4(v, uh, ul);
            *(uint2*)(ohi + off) = uh;
            *(uint2*)(olo + off) = ul;
        }
    }
}

// ---------------- global add pool ----------------
__global__ void __launch_bounds__(128) pool_kernel(
    const float* __restrict__ h, const int* __restrict__ batch,
    float* __restrict__ g) {
    int c = threadIdx.x;
    int n0 = blockIdx.x * 128;
    int nend = min(n0 + 128, NN);
    float local = 0.f;
    int gprev = batch[n0];
    for (int n = n0; n < nend; n++) {
        int gb = batch[n];
        if (gb != gprev) {
            atomicAdd(&g[gprev * HH + c], local);
            local = 0.f; gprev = gb;
        }
        local += h[(size_t)n * HH + c];
    }
    atomicAdd(&g[gprev * HH + c], local);
}

// ---------------- MLP head ----------------
__global__ void __launch_bounds__(128) mlp_head_kernel(
    const float* __restrict__ g,
    const float* __restrict__ W0, const float* __restrict__ b0,
    const float* __restrict__ W1, const float* __restrict__ b1,
    const float* __restrict__ hw, const float* __restrict__ hb,
    float* __restrict__ out) {
    __shared__ float sg[HH];
    __shared__ float st[HH];
    __shared__ float red[4];
    int b = blockIdx.x, t = threadIdx.x;
    sg[t] = g[b * HH + t];
    __syncthreads();
    float s = 0.f;
#pragma unroll 8
    for (int k = 0; k < HH; k++) s = fmaf(sg[k], W0[k * HH + t], s);
    s = fmaxf(s + b0[t], 0.f);
    st[t] = s;
    __syncthreads();
    float s2 = 0.f;
#pragma unroll 8
    for (int k = 0; k < HH; k++) s2 = fmaf(st[k], W1[k * HH + t], s2);
    s2 = fmaxf(s2 + b1[t], 0.f);
    float p = s2 * hw[t];
#pragma unroll
    for (int o = 16; o > 0; o >>= 1) p += __shfl_xor_sync(0xffffffffu, p, o);
    if ((t & 31) == 0) red[t >> 5] = p;
    __syncthreads();
    if (t == 0) out[b] = red[0] + red[1] + red[2] + red[3] + hb[0];
}

// ---------------- host launcher ----------------
extern "C" void kernel_launch(void* const* d_in, const int* in_sizes, int n_in,
                              void* d_out, int out_size) {
    const float* x     = (const float*)d_in[0];
    const int*   eic   = (const int*)d_in[1];
    const int*   eid   = (const int*)d_in[2];
    const int*   eit   = (const int*)d_in[3];
    const int*   batch = (const int*)d_in[4];
    const float *Wl[5], *bl[5], *Wr[5];
    for (int c = 0; c < 5; c++) {
        Wl[c] = (const float*)d_in[5 + 3 * c];
        bl[c] = (const float*)d_in[6 + 3 * c];
        Wr[c] = (const float*)d_in[7 + 3 * c];
    }
    const float* l0W = (const float*)d_in[20];
    const float* l0b = (const float*)d_in[21];
    const float* l1W = (const float*)d_in[22];
    const float* l1b = (const float*)d_in[23];
    const float* hW  = (const float*)d_in[24];
    const float* hb  = (const float*)d_in[25];

    float *h, *tmp, *invc, *g;
    bf16 *xhi, *xlo, *ahi, *alo, *Whi, *Wlo;
    int *rowptr, *cur, *csum, *ssrc;
    cudaGetSymbolAddress((void**)&h, d_h);
    cudaGetSymbolAddress((void**)&tmp, d_tmp);
    cudaGetSymbolAddress((void**)&xhi, d_xhi);
    cudaGetSymbolAddress((void**)&xlo, d_xlo);
    cudaGetSymbolAddress((void**)&ahi, d_ahi);
    cudaGetSymbolAddress((void**)&alo, d_alo);
    cudaGetSymbolAddress((void**)&Whi, d_Whi);
    cudaGetSymbolAddress((void**)&Wlo, d_Wlo);
    cudaGetSymbolAddress((void**)&rowptr, d_rowptr);
    cudaGetSymbolAddress((void**)&cur, d_cur);
    cudaGetSymbolAddress((void**)&csum, d_csum);
    cudaGetSymbolAddress((void**)&ssrc, d_ssrc);
    cudaGetSymbolAddress((void**)&invc, d_invc);
    cudaGetSymbolAddress((void**)&g, d_g);

    const int SM1 = 1024 + 2 * STAGE_BYTES;          // 38912
    const int SM2 = 1024 + 128 * CP * 4;             // 70656
    cudaFuncSetAttribute(layer_k1, cudaFuncAttributeMaxDynamicSharedMemorySize, SM1);
    cudaFuncSetAttribute(layer_k2, cudaFuncAttributeMaxDynamicSharedMemorySize, SM2);

    // CSR build
    zero_int_kernel<<<(3 * NN + 255) / 256, 256>>>(cur, 3 * NN);
    hist3_kernel<<<(3 * EE + 255) / 256, 256>>>(eic, eid, eit, cur);
    chunksum_kernel<<<3 * NCHUNK, 256>>>(cur, csum);
    chunkscan_kernel<<<3, 256>>>(csum, rowptr);
    applyscan_kernel<<<3 * NCHUNK, 256>>>(csum, cur, rowptr, invc);
    fill3_kernel<<<(3 * EE + 255) / 256, 256>>>(eic, eid, eit, cur, ssrc);

    // conversions
    for (int c = 0; c < 5; c++)
        convW_kernel<<<32, 256>>>(Wl[c], Wr[c],
                                  Whi + c * 256 * HH, Wlo + c * 256 * HH);
    convX_kernel<<<(NN * 32 + 255) / 256, 256>>>(x, xhi, xlo);

    // 7 SAGE layers
    const int set_of[7]  = {1, 0, 0, 2, 1, 0, 0};
    const int conv_of[7] = {0, 1, 1, 2, 3, 4, 4};
    const int norm_of[7] = {1, 1, 1, 0, 1, 1, 1};

    const int K1_GRID = 6250 + 391;   // gather blocks + x-gemm blocks
    const float* cin = x;
    for (int l = 0; l < 7; l++) {
        int s = set_of[l], c = conv_of[l];
        layer_k1<<<K1_GRID, 256, SM1>>>(
            cin, rowptr + s * (NN + 1), ssrc + (size_t)s * EE, invc + s * NN,
            ahi, alo, xhi, xlo,
            Whi + c * 256 * HH, Wlo + c * 256 * HH, tmp);
        layer_k2<<<(NN + 127) / 128, 256, SM2>>>(
            ahi, alo, Whi + c * 256 * HH, Wlo + c * 256 * HH,
            tmp, bl[c], norm_of[l], h, xhi, xlo);
        cin = h;
    }

    // pool + MLP + head
    zero_float_kernel<<<(GG * HH + 255) / 256, 256>>>(g, GG * HH);
    pool_kernel<<<(NN + 127) / 128, 128>>>(cin, batch, g);
    mlp_head_kernel<<<GG, 128>>>(g, l0W, l0b, l1W, l1b, hW, hb, (float*)d_out);
}